// round 7
// baseline (speedup 1.0000x reference)
#include <cuda_runtime.h>
#include <cuda_bf16.h>

// Problem constants
#define TOTAL_N 262144      // B*N nodes
#define NEDGE   4194304
#define NPTS    32768       // N
#define CBOUT   128
#define NSTATS  90          // 12 sums + 78 upper-triangle second moments

// Bucketing: 64 buckets x 4096 nodes; 512 build blocks x 8192 edges
#define NBUCKET 64
#define BSHIFT  12          // dst >> 12 = bucket
#define BNODES  4096
#define NBLK    512
#define EPB     8192        // edges per build block

// ---------------------------------------------------------------------------
// Device scratch (static allocations only)
// ---------------------------------------------------------------------------
__device__ float  g_deg[TOTAL_N];
__device__ float  g_dis[TOTAL_N];
__device__ float4 g_t0[TOTAL_N];
__device__ float4 g_t1[TOTAL_N];
__device__ float4 g_t2[TOTAL_N];
__device__ float4 g_t3[TOTAL_N];
__device__ float4 g_q[TOTAL_N];     // dis-scaled current Chebyshev vector
__device__ float4 g_acc[TOTAL_N];   // edge-pass accumulator
__device__ uint2  g_erec[NEDGE];    // bucketed edge records {src|dstlow<<18, w}
__device__ int    g_cnt[NBLK * NBUCKET];   // per-(block,bucket) counts
__device__ int    g_off[NBLK * NBUCKET];   // per-(block,bucket) excl. prefix within bucket
__device__ int    g_btot[NBUCKET];
__device__ int    g_bbase[NBUCKET + 1];
__device__ double g_stats[NSTATS];
__device__ float  g_wfT[CBOUT * 12];
__device__ float  g_sh[CBOUT];

__device__ __forceinline__ void red_v4(float4* addr, float x, float y, float z) {
    asm volatile("red.global.add.v4.f32 [%0], {%1, %2, %3, %4};"
                 :: "l"(addr), "f"(x), "f"(y), "f"(z), "f"(0.f) : "memory");
}

// ---------------------------------------------------------------------------
// 1) init: zero degree, accumulator, stats
// ---------------------------------------------------------------------------
__global__ void k_init() {
    int i = blockIdx.x * blockDim.x + threadIdx.x;   // TOTAL_N threads
    g_deg[i] = 0.f;
    g_acc[i] = make_float4(0.f, 0.f, 0.f, 0.f);
    if (i < NSTATS) g_stats[i] = 0.0;
}

// ---------------------------------------------------------------------------
// 2) fused degree + bucket histogram.
//    deg[src] += w (self-loops skipped); cnt[blk][bucket(dst)]++
// ---------------------------------------------------------------------------
__global__ __launch_bounds__(256) void k_deg_hist(const int* __restrict__ src,
                                                  const int* __restrict__ dst,
                                                  const float* __restrict__ ew) {
    __shared__ int h[NBUCKET];
    int blk = blockIdx.x, tid = threadIdx.x;
    if (tid < NBUCKET) h[tid] = 0;
    __syncthreads();
    int base = blk * EPB;
#pragma unroll 4
    for (int i = 0; i < 32; i++) {
        int j = base + i * 256 + tid;
        int s = src[j], d = dst[j];
        float w = ew[j];
        atomicAdd(&h[d >> BSHIFT], 1);
        if (s != d) atomicAdd(&g_deg[s], w);
    }
    __syncthreads();
    if (tid < NBUCKET) g_cnt[blk * NBUCKET + tid] = h[tid];
}

// ---------------------------------------------------------------------------
// 3) scan 1: per bucket, exclusive prefix of the 512 block counts.
//    64 blocks (one per bucket) x 128 threads, 4 counts per thread.
// ---------------------------------------------------------------------------
__global__ void k_scan1() {
    int b = blockIdx.x;
    int t = threadIdx.x;
    __shared__ int part[128];
    int c[4];
    int base = 4 * t;
#pragma unroll
    for (int k = 0; k < 4; k++) c[k] = g_cnt[(base + k) * NBUCKET + b];
    int s = c[0] + c[1] + c[2] + c[3];
    part[t] = s;
    __syncthreads();
    // Hillis-Steele inclusive scan over 128 partials
    for (int off = 1; off < 128; off <<= 1) {
        int v = (t >= off) ? part[t - off] : 0;
        __syncthreads();
        part[t] += v;
        __syncthreads();
    }
    int run = part[t] - s;   // exclusive prefix of this thread's chunk
#pragma unroll
    for (int k = 0; k < 4; k++) { g_off[(base + k) * NBUCKET + b] = run; run += c[k]; }
    if (t == 127) g_btot[b] = run;
}

// ---------------------------------------------------------------------------
// 4) scan 2: bucket bases (exclusive scan of 64 totals). 1 block, 64 threads.
// ---------------------------------------------------------------------------
__global__ void k_scan2() {
    int t = threadIdx.x;
    __shared__ int sm[NBUCKET];
    int v = g_btot[t];
    sm[t] = v;
    __syncthreads();
    for (int off = 1; off < NBUCKET; off <<= 1) {
        int u = (t >= off) ? sm[t - off] : 0;
        __syncthreads();
        sm[t] += u;
        __syncthreads();
    }
    g_bbase[t] = sm[t] - v;
    if (t == NBUCKET - 1) g_bbase[NBUCKET] = sm[t];
}

// ---------------------------------------------------------------------------
// 5) scatter edges into bucketed record array (exact offsets, no slack).
//    Record: {src(18b) | dstlow(12b)<<18, w} with self-loop w zeroed.
// ---------------------------------------------------------------------------
__global__ __launch_bounds__(256) void k_scatter(const int* __restrict__ src,
                                                 const int* __restrict__ dst,
                                                 const float* __restrict__ ew) {
    __shared__ int cur[NBUCKET];
    int blk = blockIdx.x, tid = threadIdx.x;
    if (tid < NBUCKET) cur[tid] = g_off[blk * NBUCKET + tid] + g_bbase[tid];
    __syncthreads();
    int base = blk * EPB;
#pragma unroll 4
    for (int i = 0; i < 32; i++) {
        int j = base + i * 256 + tid;
        int s = src[j], d = dst[j];
        float w = ew[j];
        if (s == d) w = 0.f;
        int b = d >> BSHIFT;
        int pos = atomicAdd(&cur[b], 1);
        uint2 r;
        r.x = (unsigned)s | ((unsigned)(d & (BNODES - 1)) << 18);
        r.y = __float_as_uint(w);
        g_erec[pos] = r;
    }
}

// ---------------------------------------------------------------------------
// 6) node pass 0: dis, T0 = x, q = dis*T0
// ---------------------------------------------------------------------------
__global__ void k_node0(const float* __restrict__ x) {
    int i = blockIdx.x * blockDim.x + threadIdx.x;   // TOTAL_N threads
    float dg  = g_deg[i];
    float dis = (dg > 0.f) ? rsqrtf(fmaxf(dg, 1e-12f)) : 0.f;
    g_dis[i] = dis;
    int b = i >> 15;
    int n = i & (NPTS - 1);
    const float* xb = x + (size_t)b * 3 * NPTS + n;
    float v0 = xb[0];
    float v1 = xb[NPTS];
    float v2 = xb[2 * NPTS];
    g_t0[i] = make_float4(v0, v1, v2, 0.f);
    g_q[i]  = make_float4(dis * v0, dis * v1, dis * v2, 0.f);
}

// ---------------------------------------------------------------------------
// 7) bucketed edge pass: smem-accumulate w*q[src] by dstlow, flush vector REDs.
//    grid = 64 buckets x 4 parts; 48KB smem slice per block.
//    8-deep gather batching keeps the L2 queue saturated.
// ---------------------------------------------------------------------------
__global__ __launch_bounds__(256) void k_edgeB() {
    __shared__ float ax[BNODES], ay[BNODES], az[BNODES];
    int g = blockIdx.x, tid = threadIdx.x;
    int b = g >> 2, part = g & 3;
    int lo0 = g_bbase[b], hi0 = g_bbase[b + 1];
    int len = hi0 - lo0;
    int lo = lo0 + (int)(((long long)len * part) >> 2);
    int hi = lo0 + (int)(((long long)len * (part + 1)) >> 2);

    for (int k = tid; k < BNODES; k += 256) { ax[k] = 0.f; ay[k] = 0.f; az[k] = 0.f; }
    __syncthreads();

    for (int j = lo + tid; j < hi; j += 2048) {
        uint2  r[8];
        float4 q[8];
#pragma unroll
        for (int k = 0; k < 8; k++) {
            int j2 = j + k * 256;
            if (j2 < hi) r[k] = g_erec[j2];
        }
#pragma unroll
        for (int k = 0; k < 8; k++) {
            int j2 = j + k * 256;
            if (j2 < hi) q[k] = g_q[r[k].x & 0x3FFFFu];
        }
#pragma unroll
        for (int k = 0; k < 8; k++) {
            int j2 = j + k * 256;
            if (j2 < hi) {
                int dl  = (r[k].x >> 18) & (BNODES - 1);
                float w = __uint_as_float(r[k].y);
                atomicAdd(&ax[dl], w * q[k].x);
                atomicAdd(&ay[dl], w * q[k].y);
                atomicAdd(&az[dl], w * q[k].z);
            }
        }
    }
    __syncthreads();

    int nb = b << BSHIFT;
    for (int k = tid; k < BNODES; k += 256)
        red_v4(&g_acc[nb + k], ax[k], ay[k], az[k]);
}

// ---------------------------------------------------------------------------
// 8) node pass 1: T1 = -dis*acc ; q = dis*T1 ; acc = 0
// ---------------------------------------------------------------------------
__global__ void k_node1() {
    int i = blockIdx.x * blockDim.x + threadIdx.x;
    float4 a  = g_acc[i];
    float dis = g_dis[i];
    float x = -dis * a.x, y = -dis * a.y, z = -dis * a.z;
    g_t1[i]  = make_float4(x, y, z, 0.f);
    g_q[i]   = make_float4(dis * x, dis * y, dis * z, 0.f);
    g_acc[i] = make_float4(0.f, 0.f, 0.f, 0.f);
}

// ---------------------------------------------------------------------------
// 9) node pass 2: T2 = -2*dis*acc - T0 ; q = dis*T2 ; acc = 0
// ---------------------------------------------------------------------------
__global__ void k_node2() {
    int i = blockIdx.x * blockDim.x + threadIdx.x;
    float4 a  = g_acc[i];
    float dis = g_dis[i];
    float4 t0 = g_t0[i];
    float x = -2.f * dis * a.x - t0.x;
    float y = -2.f * dis * a.y - t0.y;
    float z = -2.f * dis * a.z - t0.z;
    g_t2[i]  = make_float4(x, y, z, 0.f);
    g_q[i]   = make_float4(dis * x, dis * y, dis * z, 0.f);
    g_acc[i] = make_float4(0.f, 0.f, 0.f, 0.f);
}

// ---------------------------------------------------------------------------
// 10) node pass 3 + stats fused: T3 = -2*dis*acc - T1, then Σv, Σvvᵀ.
// ---------------------------------------------------------------------------
__global__ __launch_bounds__(128) void k_node3_stats() {
    int t = blockIdx.x * 128 + threadIdx.x;          // 32768 threads
    float acc[NSTATS];
#pragma unroll
    for (int k = 0; k < NSTATS; k++) acc[k] = 0.f;

    for (int it = 0; it < 8; it++) {
        int i = t + it * 32768;
        float4 a  = g_acc[i];
        float dis = g_dis[i];
        float4 b  = g_t1[i];
        float tx = -2.f * dis * a.x - b.x;
        float ty = -2.f * dis * a.y - b.y;
        float tz = -2.f * dis * a.z - b.z;
        g_t3[i] = make_float4(tx, ty, tz, 0.f);

        float v[12];
        float4 p = g_t0[i]; v[0] = p.x; v[1] = p.y; v[2]  = p.z;
        v[3] = b.x; v[4] = b.y; v[5] = b.z;
        float4 c = g_t2[i]; v[6] = c.x; v[7] = c.y; v[8]  = c.z;
        v[9] = tx; v[10] = ty; v[11] = tz;
        int idx = 12;
#pragma unroll
        for (int p2 = 0; p2 < 12; p2++) {
            acc[p2] += v[p2];
#pragma unroll
            for (int q = p2; q < 12; q++) acc[idx++] += v[p2] * v[q];
        }
    }
    int lane = threadIdx.x & 31;
#pragma unroll
    for (int k = 0; k < NSTATS; k++) {
        float x = acc[k];
        x += __shfl_down_sync(0xffffffffu, x, 16);
        x += __shfl_down_sync(0xffffffffu, x, 8);
        x += __shfl_down_sync(0xffffffffu, x, 4);
        x += __shfl_down_sync(0xffffffffu, x, 2);
        x += __shfl_down_sync(0xffffffffu, x, 1);
        if (lane == 0) atomicAdd(&g_stats[k], (double)x);
    }
}

// ---------------------------------------------------------------------------
// 11) BN params: fold exact batch mean/var into scale/shift.
//     shift = beta − m·scale (conv bias cancels against batch mean)
// ---------------------------------------------------------------------------
__global__ void k_bnparam(const float* __restrict__ weight,  // (12, 128)
                          const float* __restrict__ bias,
                          const float* __restrict__ gamma,
                          const float* __restrict__ beta) {
    __shared__ double S[NSTATS];
    int c = threadIdx.x;                              // 128 threads
    if (c < NSTATS) S[c] = g_stats[c];
    __syncthreads();

    double wv[12];
#pragma unroll
    for (int a = 0; a < 12; a++) wv[a] = (double)weight[a * CBOUT + c];

    const double invN = 1.0 / (double)TOTAL_N;
    double m = 0.0;
#pragma unroll
    for (int a = 0; a < 12; a++) m += S[a] * wv[a];
    m *= invN;

    double q = 0.0;
    int idx = 12;
#pragma unroll
    for (int a = 0; a < 12; a++) {
#pragma unroll
        for (int b = a; b < 12; b++) {
            double term = S[idx++] * wv[a] * wv[b];
            q += (a == b) ? term : 2.0 * term;
        }
    }
    q *= invN;

    double var = q - m * m;
    if (var < 0.0) var = 0.0;
    (void)bias;
    double scale = (double)gamma[c] * rsqrt(var + 1e-5);
    g_sh[c] = (float)((double)beta[c] - m * scale);
#pragma unroll
    for (int a = 0; a < 12; a++)
        g_wfT[c * 12 + a] = (float)(wv[a] * scale);
}

// ---------------------------------------------------------------------------
// 12) final fused GEMV + BN + ReLU, writing directly in (B, C_OUT, N) layout.
// ---------------------------------------------------------------------------
__global__ __launch_bounds__(256) void k_final(float* __restrict__ out) {
    __shared__ __align__(16) float swf[CBOUT * 12];
    __shared__ float ssh[CBOUT];

    int tid = threadIdx.x;
    for (int k = tid; k < CBOUT * 12; k += 256) swf[k] = g_wfT[k];
    if (tid < CBOUT) ssh[tid] = g_sh[tid];
    __syncthreads();

    int w    = tid >> 5;
    int lane = tid & 31;
    int j    = (w & 3) * 32 + lane;
    int cg   = w >> 2;
    int i    = blockIdx.x * 128 + j;

    float4 a = g_t0[i], b = g_t1[i], c = g_t2[i], d = g_t3[i];
    float v[12] = { a.x, a.y, a.z,  b.x, b.y, b.z,
                    c.x, c.y, c.z,  d.x, d.y, d.z };

    int bb = i >> 15;
    int n  = i & (NPTS - 1);
    float* obase = out + ((size_t)bb * CBOUT) * NPTS + n;

#pragma unroll 8
    for (int k = 0; k < 64; k++) {
        int ch = cg * 64 + k;
        const float4* wr = (const float4*)(swf + ch * 12);
        float4 w0 = wr[0], w1 = wr[1], w2 = wr[2];
        float r = ssh[ch];
        r += v[0] * w0.x + v[1]  * w0.y + v[2]  * w0.z + v[3] * w0.w;
        r += v[4] * w1.x + v[5]  * w1.y + v[6]  * w1.z + v[7] * w1.w;
        r += v[8] * w2.x + v[9]  * w2.y + v[10] * w2.z + v[11] * w2.w;
        obase[(size_t)ch * NPTS] = fmaxf(r, 0.f);
    }
}

// ---------------------------------------------------------------------------
// launch
// ---------------------------------------------------------------------------
extern "C" void kernel_launch(void* const* d_in, const int* in_sizes, int n_in,
                              void* d_out, int out_size) {
    const float* x      = (const float*)d_in[0];
    const int*   eidx   = (const int*)d_in[1];
    const float* ew     = (const float*)d_in[2];
    const float* weight = (const float*)d_in[3];
    const float* bias   = (const float*)d_in[4];
    const float* gamma  = (const float*)d_in[5];
    const float* beta   = (const float*)d_in[6];
    float* out = (float*)d_out;

    const int* src = eidx;          // edge_index[0]
    const int* dst = eidx + NEDGE;  // edge_index[1]

    dim3 bN(256);
    dim3 gN(TOTAL_N / 256);         // 1024 blocks (node kernels)

    k_init    <<<gN, bN>>>();
    k_deg_hist<<<NBLK, bN>>>(src, dst, ew);   // deg + bucket histogram
    k_scan1   <<<NBUCKET, 128>>>();           // per-bucket block-offsets
    k_scan2   <<<1, NBUCKET>>>();             // bucket bases
    k_scatter <<<NBLK, bN>>>(src, dst, ew);   // build bucketed records
    k_node0   <<<gN, bN>>>(x);                // dis, T0, q0
    k_edgeB   <<<NBUCKET * 4, bN>>>();        // acc = A_w q0
    k_node1   <<<gN, bN>>>();                 // T1, q1
    k_edgeB   <<<NBUCKET * 4, bN>>>();        // acc = A_w q1
    k_node2   <<<gN, bN>>>();                 // T2, q2
    k_edgeB   <<<NBUCKET * 4, bN>>>();        // acc = A_w q2
    k_node3_stats <<<256, 128>>>();           // T3 + BN stats
    k_bnparam <<<1, 128>>>(weight, bias, gamma, beta);
    k_final   <<<TOTAL_N / 128, 256>>>(out);
}

// round 8
// speedup vs baseline: 1.0292x; 1.0292x over previous
#include <cuda_runtime.h>

// Problem constants
#define TOTAL_N 262144      // B*N nodes
#define NEDGE   4194304
#define NEDGE4  1048576     // NEDGE/4 (int4 groups)
#define NPTS    32768
#define CBOUT   128
#define NSTATS  90          // 12 sums + 78 upper-triangle second moments

// Persistent kernel A: 148 SMs x 4 blocks, residency forced by launch_bounds
#define GRID_A  592
#define NT_A    256
#define NTHR_A  (GRID_A * NT_A)     // 151552

// Kernel B (stats+bnparam): higher regs -> 2..4 blocks/SM cap, small grid
#define GRID_B  296
#define NT_B    128
#define NTHR_B  (GRID_B * NT_B)     // 37888

// ---------------------------------------------------------------------------
// Device scratch (static allocations only)
// ---------------------------------------------------------------------------
__device__ float  g_deg[TOTAL_N];
__device__ float  g_dis[TOTAL_N];
__device__ float4 g_t0[TOTAL_N];
__device__ float4 g_t1[TOTAL_N];
__device__ float4 g_t2[TOTAL_N];
__device__ float4 g_t3[TOTAL_N];
__device__ float4 g_q[TOTAL_N];     // dis-scaled current Chebyshev vector
__device__ float4 g_acc[TOTAL_N];   // edge-pass accumulator
__device__ double g_stats[NSTATS];
__device__ float  g_wfT[CBOUT * 12];
__device__ float  g_sh[CBOUT];

// software grid barrier state (module-load init; cnt returns to 0 after each use)
__device__ int           g_bcnt = 0;
__device__ volatile int  g_bgen = 0;

__device__ __forceinline__ void red_v4(float4* addr, float x, float y, float z) {
    asm volatile("red.global.add.v4.f32 [%0], {%1, %2, %3, %4};"
                 :: "l"(addr), "f"(x), "f"(y), "f"(z), "f"(0.f) : "memory");
}

// Grid-wide barrier. Safe because the full grid is co-resident
// (launch_bounds guarantees blocks/SM, grid == 148 * blocks/SM).
__device__ __forceinline__ void gbar(int nblk) {
    __syncthreads();
    if (threadIdx.x == 0) {
        __threadfence();                      // publish prior writes (incl. REDs)
        int gen = g_bgen;
        if (atomicAdd(&g_bcnt, 1) == nblk - 1) {
            g_bcnt = 0;
            __threadfence();
            g_bgen = gen + 1;                 // release
        } else {
            while (g_bgen == gen) { __nanosleep(64); }
        }
        __threadfence();
    }
    __syncthreads();
}

// ---------------------------------------------------------------------------
// shared edge-propagation phase: acc[dst] += w * q[src], 8 edges/iteration
// ---------------------------------------------------------------------------
__device__ __forceinline__ void edge_prop(const int4* __restrict__ s4,
                                          const int4* __restrict__ d4,
                                          const float4* __restrict__ w4,
                                          int t) {
    for (int g = t; g < NEDGE4; g += 2 * NTHR_A) {
        int g2 = g + NTHR_A;
        bool ok = (g2 < NEDGE4);
        int4   sa = s4[g], da = d4[g];
        float4 wa = w4[g];
        int4   sb = sa, db = da;
        float4 wb = make_float4(0.f, 0.f, 0.f, 0.f);
        if (ok) { sb = s4[g2]; db = d4[g2]; wb = w4[g2]; }
        wa.x = (sa.x == da.x) ? 0.f : wa.x;
        wa.y = (sa.y == da.y) ? 0.f : wa.y;
        wa.z = (sa.z == da.z) ? 0.f : wa.z;
        wa.w = (sa.w == da.w) ? 0.f : wa.w;
        wb.x = (sb.x == db.x) ? 0.f : wb.x;
        wb.y = (sb.y == db.y) ? 0.f : wb.y;
        wb.z = (sb.z == db.z) ? 0.f : wb.z;
        wb.w = (sb.w == db.w) ? 0.f : wb.w;

        // batch the 8 random gathers (L2-only: q is rewritten across phases)
        float4 q0 = __ldcg(&g_q[sa.x]);
        float4 q1 = __ldcg(&g_q[sa.y]);
        float4 q2 = __ldcg(&g_q[sa.z]);
        float4 q3 = __ldcg(&g_q[sa.w]);
        float4 q4, q5, q6, q7;
        if (ok) {
            q4 = __ldcg(&g_q[sb.x]);
            q5 = __ldcg(&g_q[sb.y]);
            q6 = __ldcg(&g_q[sb.z]);
            q7 = __ldcg(&g_q[sb.w]);
        }

        red_v4(&g_acc[da.x], wa.x * q0.x, wa.x * q0.y, wa.x * q0.z);
        red_v4(&g_acc[da.y], wa.y * q1.x, wa.y * q1.y, wa.y * q1.z);
        red_v4(&g_acc[da.z], wa.z * q2.x, wa.z * q2.y, wa.z * q2.z);
        red_v4(&g_acc[da.w], wa.w * q3.x, wa.w * q3.y, wa.w * q3.z);
        if (ok) {
            red_v4(&g_acc[db.x], wb.x * q4.x, wb.x * q4.y, wb.x * q4.z);
            red_v4(&g_acc[db.y], wb.y * q5.x, wb.y * q5.y, wb.y * q5.z);
            red_v4(&g_acc[db.z], wb.z * q6.x, wb.z * q6.y, wb.z * q6.z);
            red_v4(&g_acc[db.w], wb.w * q7.x, wb.w * q7.y, wb.w * q7.z);
        }
    }
}

// ---------------------------------------------------------------------------
// Kernel A: init -> deg -> node0 -> e1 -> node1 -> e2 -> node2 -> e3
// ---------------------------------------------------------------------------
__global__ __launch_bounds__(NT_A, 4) void kA(const float* __restrict__ x,
                                              const int* __restrict__ src,
                                              const int* __restrict__ dst,
                                              const float* __restrict__ ew) {
    const int t = blockIdx.x * NT_A + threadIdx.x;
    const int4*   s4 = (const int4*)src;
    const int4*   d4 = (const int4*)dst;
    const float4* w4 = (const float4*)ew;

    // phase: init
    for (int i = t; i < TOTAL_N; i += NTHR_A) {
        g_deg[i] = 0.f;
        g_acc[i] = make_float4(0.f, 0.f, 0.f, 0.f);
    }
    if (t < NSTATS) g_stats[t] = 0.0;
    gbar(GRID_A);

    // phase: degree  deg[src] += w (self-loops skipped)
    for (int g = t; g < NEDGE4; g += 2 * NTHR_A) {
        int g2 = g + NTHR_A;
        bool ok = (g2 < NEDGE4);
        int4   sa = s4[g], da = d4[g];
        float4 wa = w4[g];
        int4   sb = sa, db = da;
        float4 wb = make_float4(0.f, 0.f, 0.f, 0.f);
        if (ok) { sb = s4[g2]; db = d4[g2]; wb = w4[g2]; }
        if (sa.x != da.x) atomicAdd(&g_deg[sa.x], wa.x);
        if (sa.y != da.y) atomicAdd(&g_deg[sa.y], wa.y);
        if (sa.z != da.z) atomicAdd(&g_deg[sa.z], wa.z);
        if (sa.w != da.w) atomicAdd(&g_deg[sa.w], wa.w);
        if (ok) {
            if (sb.x != db.x) atomicAdd(&g_deg[sb.x], wb.x);
            if (sb.y != db.y) atomicAdd(&g_deg[sb.y], wb.y);
            if (sb.z != db.z) atomicAdd(&g_deg[sb.z], wb.z);
            if (sb.w != db.w) atomicAdd(&g_deg[sb.w], wb.w);
        }
    }
    gbar(GRID_A);

    // phase: node0  dis, T0 = x, q = dis*T0
    for (int i = t; i < TOTAL_N; i += NTHR_A) {
        float dg  = __ldcg(&g_deg[i]);            // written via REDs from all blocks
        float dis = (dg > 0.f) ? rsqrtf(fmaxf(dg, 1e-12f)) : 0.f;
        g_dis[i] = dis;
        int b = i >> 15;
        int n = i & (NPTS - 1);
        const float* xb = x + (size_t)b * 3 * NPTS + n;
        float v0 = xb[0];
        float v1 = xb[NPTS];
        float v2 = xb[2 * NPTS];
        g_t0[i] = make_float4(v0, v1, v2, 0.f);
        g_q[i]  = make_float4(dis * v0, dis * v1, dis * v2, 0.f);
    }
    gbar(GRID_A);

    edge_prop(s4, d4, w4, t);                     // acc = A_w q0
    gbar(GRID_A);

    // phase: node1  T1 = -dis*acc ; q = dis*T1 ; acc = 0
    for (int i = t; i < TOTAL_N; i += NTHR_A) {
        float4 a  = __ldcg(&g_acc[i]);
        float dis = g_dis[i];
        float vx = -dis * a.x, vy = -dis * a.y, vz = -dis * a.z;
        g_t1[i]  = make_float4(vx, vy, vz, 0.f);
        g_q[i]   = make_float4(dis * vx, dis * vy, dis * vz, 0.f);
        g_acc[i] = make_float4(0.f, 0.f, 0.f, 0.f);
    }
    gbar(GRID_A);

    edge_prop(s4, d4, w4, t);                     // acc = A_w q1
    gbar(GRID_A);

    // phase: node2  T2 = -2*dis*acc - T0 ; q = dis*T2 ; acc = 0
    for (int i = t; i < TOTAL_N; i += NTHR_A) {
        float4 a  = __ldcg(&g_acc[i]);
        float dis = g_dis[i];
        float4 t0 = g_t0[i];
        float vx = -2.f * dis * a.x - t0.x;
        float vy = -2.f * dis * a.y - t0.y;
        float vz = -2.f * dis * a.z - t0.z;
        g_t2[i]  = make_float4(vx, vy, vz, 0.f);
        g_q[i]   = make_float4(dis * vx, dis * vy, dis * vz, 0.f);
        g_acc[i] = make_float4(0.f, 0.f, 0.f, 0.f);
    }
    gbar(GRID_A);

    edge_prop(s4, d4, w4, t);                     // acc = A_w q2 (kernel end syncs)
}

// ---------------------------------------------------------------------------
// Kernel B: T3 + BN stats, then fold BN params.
// ---------------------------------------------------------------------------
__global__ __launch_bounds__(NT_B, 4) void kB(const float* __restrict__ weight,
                                              const float* __restrict__ gamma,
                                              const float* __restrict__ beta) {
    int t = blockIdx.x * NT_B + threadIdx.x;
    float acc[NSTATS];
#pragma unroll
    for (int k = 0; k < NSTATS; k++) acc[k] = 0.f;

    for (int i = t; i < TOTAL_N; i += NTHR_B) {
        float4 a  = __ldcg(&g_acc[i]);
        float dis = g_dis[i];
        float4 b  = g_t1[i];
        float tx = -2.f * dis * a.x - b.x;
        float ty = -2.f * dis * a.y - b.y;
        float tz = -2.f * dis * a.z - b.z;
        g_t3[i] = make_float4(tx, ty, tz, 0.f);

        float v[12];
        float4 p = g_t0[i]; v[0] = p.x; v[1] = p.y; v[2]  = p.z;
        v[3] = b.x; v[4] = b.y; v[5] = b.z;
        float4 c = g_t2[i]; v[6] = c.x; v[7] = c.y; v[8]  = c.z;
        v[9] = tx; v[10] = ty; v[11] = tz;
        int idx = 12;
#pragma unroll
        for (int p2 = 0; p2 < 12; p2++) {
            acc[p2] += v[p2];
#pragma unroll
            for (int q = p2; q < 12; q++) acc[idx++] += v[p2] * v[q];
        }
    }
    int lane = threadIdx.x & 31;
#pragma unroll
    for (int k = 0; k < NSTATS; k++) {
        float xv = acc[k];
        xv += __shfl_down_sync(0xffffffffu, xv, 16);
        xv += __shfl_down_sync(0xffffffffu, xv, 8);
        xv += __shfl_down_sync(0xffffffffu, xv, 4);
        xv += __shfl_down_sync(0xffffffffu, xv, 2);
        xv += __shfl_down_sync(0xffffffffu, xv, 1);
        if (lane == 0) atomicAdd(&g_stats[k], (double)xv);
    }
    gbar(GRID_B);

    // BN fold (block 0 only, 128 threads = 128 channels)
    if (blockIdx.x == 0) {
        __shared__ double S[NSTATS];
        int c = threadIdx.x;
        if (c < NSTATS) S[c] = g_stats[c];
        __syncthreads();

        double wv[12];
#pragma unroll
        for (int a = 0; a < 12; a++) wv[a] = (double)weight[a * CBOUT + c];

        const double invN = 1.0 / (double)TOTAL_N;
        double m = 0.0;
#pragma unroll
        for (int a = 0; a < 12; a++) m += S[a] * wv[a];
        m *= invN;

        double q = 0.0;
        int idx = 12;
#pragma unroll
        for (int a = 0; a < 12; a++) {
#pragma unroll
            for (int b = a; b < 12; b++) {
                double term = S[idx++] * wv[a] * wv[b];
                q += (a == b) ? term : 2.0 * term;
            }
        }
        q *= invN;

        double var = q - m * m;
        if (var < 0.0) var = 0.0;
        // conv bias cancels between pre-BN value and batch mean
        double scale = (double)gamma[c] * rsqrt(var + 1e-5);
        g_sh[c] = (float)((double)beta[c] - m * scale);
#pragma unroll
        for (int a = 0; a < 12; a++)
            g_wfT[c * 12 + a] = (float)(wv[a] * scale);
    }
}

// ---------------------------------------------------------------------------
// Kernel C: fused GEMV + BN + ReLU, writing directly in (B, C_OUT, N) layout.
// ---------------------------------------------------------------------------
__global__ __launch_bounds__(256) void k_final(float* __restrict__ out) {
    __shared__ __align__(16) float swf[CBOUT * 12];
    __shared__ float ssh[CBOUT];

    int tid = threadIdx.x;
    for (int k = tid; k < CBOUT * 12; k += 256) swf[k] = g_wfT[k];
    if (tid < CBOUT) ssh[tid] = g_sh[tid];
    __syncthreads();

    int w    = tid >> 5;
    int lane = tid & 31;
    int j    = (w & 3) * 32 + lane;
    int cg   = w >> 2;
    int i    = blockIdx.x * 128 + j;

    float4 a = g_t0[i], b = g_t1[i], c = g_t2[i], d = g_t3[i];
    float v[12] = { a.x, a.y, a.z,  b.x, b.y, b.z,
                    c.x, c.y, c.z,  d.x, d.y, d.z };

    int bb = i >> 15;
    int n  = i & (NPTS - 1);
    float* obase = out + ((size_t)bb * CBOUT) * NPTS + n;

#pragma unroll 8
    for (int k = 0; k < 64; k++) {
        int ch = cg * 64 + k;
        const float4* wr = (const float4*)(swf + ch * 12);
        float4 w0 = wr[0], w1 = wr[1], w2 = wr[2];
        float r = ssh[ch];
        r += v[0] * w0.x + v[1]  * w0.y + v[2]  * w0.z + v[3] * w0.w;
        r += v[4] * w1.x + v[5]  * w1.y + v[6]  * w1.z + v[7] * w1.w;
        r += v[8] * w2.x + v[9]  * w2.y + v[10] * w2.z + v[11] * w2.w;
        obase[(size_t)ch * NPTS] = fmaxf(r, 0.f);
    }
}

// ---------------------------------------------------------------------------
// launch: 3 kernels total
// ---------------------------------------------------------------------------
extern "C" void kernel_launch(void* const* d_in, const int* in_sizes, int n_in,
                              void* d_out, int out_size) {
    const float* x      = (const float*)d_in[0];
    const int*   eidx   = (const int*)d_in[1];
    const float* ew     = (const float*)d_in[2];
    const float* weight = (const float*)d_in[3];
    const float* gamma  = (const float*)d_in[5];
    const float* beta   = (const float*)d_in[6];
    float* out = (float*)d_out;

    const int* src = eidx;          // edge_index[0]
    const int* dst = eidx + NEDGE;  // edge_index[1]

    kA<<<GRID_A, NT_A>>>(x, src, dst, ew);
    kB<<<GRID_B, NT_B>>>(weight, gamma, beta);
    k_final<<<TOTAL_N / 128, 256>>>(out);
}